// round 2
// baseline (speedup 1.0000x reference)
#include <cuda_runtime.h>
#include <math.h>

#define BATCH 256
#define SEQ   256
#define IDIM  128
#define HID   1024
#define OUTC  10

#define NCTA  128
#define NTH   256
#define MT    64
#define NT    32
#define KC    16
#define NCHUNK_H (HID / KC)            // 64
#define NCHUNK_X (IDIM / KC)           // 8
#define NCHUNK   (NCHUNK_H + NCHUNK_X) // 72
#define HALFC    (NCHUNK / 2)          // 36 chunks per K-group

// Persistent state (device globals: no allocation allowed)
__device__ float g_h[2][BATCH][HID];       // double-buffered hidden state
__device__ unsigned int g_bar;             // monotonic ticket barrier counter

// ---- packed f32x2 helpers ----
__device__ __forceinline__ unsigned long long splat2(float x) {
    unsigned long long r;
    asm("mov.b64 %0, {%1, %1};" : "=l"(r) : "f"(x));
    return r;
}
__device__ __forceinline__ void fma2(unsigned long long& acc,
                                     unsigned long long a,
                                     unsigned long long b) {
    asm("fma.rn.f32x2 %0, %1, %2, %0;" : "+l"(acc) : "l"(a), "l"(b));
}
__device__ __forceinline__ float2 unpk(unsigned long long v) {
    float2 r;
    asm("mov.b64 {%0, %1}, %2;" : "=f"(r.x), "=f"(r.y) : "l"(v));
    return r;
}

// Accurate tanh independent of fast-math tanh.approx (abs err ~5e-7).
__device__ __forceinline__ float my_tanh(float v) {
    float e = __expf(2.0f * v);
    return 1.0f - 2.0f / (e + 1.0f);
}

// group barrier: id 1 or 2, 128 threads each
__device__ __forceinline__ void group_bar(int g) {
    asm volatile("bar.sync %0, 128;" :: "r"(g + 1) : "memory");
}

// Device-wide barrier: monotonic ticket counter (survives graph replays).
__device__ __forceinline__ void grid_sync() {
    __syncthreads();
    if (threadIdx.x == 0) {
        __threadfence();
        unsigned ticket = atomicAdd(&g_bar, 1u);
        unsigned target = (ticket / NCTA + 1u) * NCTA;
        volatile unsigned* p = &g_bar;
        while (*p < target) { }
    }
    __syncthreads();
    __threadfence();
}

__global__ void __launch_bounds__(NTH, 1)
rnn_kernel(const float* __restrict__ x,      // [B,S,I]
           const float* __restrict__ Whx,    // [I,H]
           const float* __restrict__ Whh,    // [H,H]
           const float* __restrict__ bh,     // [H]
           const float* __restrict__ Why,    // [H,OUT]
           const float* __restrict__ bo,     // [OUT]
           float* __restrict__ out)          // [B,OUT]
{
    // per-group double-buffered tiles
    __shared__ __align__(16) float As[2][2][KC][MT + 4];            // k-major A
    __shared__ __align__(16) unsigned long long Bs[2][2][KC][NT];   // pre-splatted B
    __shared__ float pacc[16][NTH / 2];                              // K-split partials
    __shared__ float red[8][OUTC];

    const int tid  = threadIdx.x;
    const int bid  = blockIdx.x;
    const int grp  = tid >> 7;          // 0 or 1: K-half
    const int ltid = tid & 127;

    const int mt = bid & 3;             // 4 M-tiles of 64
    const int nt = bid >> 2;            // 32 N-tiles of 32
    const int m0 = mt * MT;
    const int n0 = nt * NT;

    // loader lanes (within group)
    const int la_m  = ltid >> 2;        // 0..31 (+32 second half)
    const int la_kt = (ltid & 3) * 4;   // 0,4,8,12
    const int lb_k  = ltid >> 3;        // 0..15
    const int lb_n  = (ltid & 7) * 4;   // 0..28

    // compute lanes: 4x4 micro-tile
    const int tx = ltid & 7;            // 8  -> 32 cols
    const int ty = ltid >> 3;           // 16 -> 64 rows

    const int cbase = grp * HALFC;      // this group's first chunk

    // ---- zero h buffer 0 (h0 = 0) ----
    {
        float4* p = (float4*)&g_h[0][0][0];
        const int total = BATCH * HID / 4;
        for (int i = bid * NTH + tid; i < total; i += NCTA * NTH)
            p[i] = make_float4(0.f, 0.f, 0.f, 0.f);
    }
    grid_sync();

    unsigned long long acc[2][4];

    for (int t = 0; t < SEQ; t++) {
        const float* __restrict__ hcur = &g_h[t & 1][0][0];
        float* __restrict__ hnxt = &g_h[(t + 1) & 1][0][0];
        const float* __restrict__ xt = x + t * IDIM;   // x[:, t, :], row stride S*I

        #pragma unroll
        for (int p = 0; p < 2; p++)
            #pragma unroll
            for (int j = 0; j < 4; j++)
                acc[p][j] = 0ull;

        float4 pA0, pA1, pB;

        // prefetch + store this group's chunk 0
        {
            const int c = cbase;
            if (c < NCHUNK_H) {
                const int k0 = c * KC;
                pA0 = *(const float4*)(hcur + (m0 + la_m) * HID + k0 + la_kt);
                pA1 = *(const float4*)(hcur + (m0 + la_m + 32) * HID + k0 + la_kt);
                pB  = *(const float4*)(Whh + (k0 + lb_k) * HID + n0 + lb_n);
            } else {
                const int k0 = (c - NCHUNK_H) * KC;
                pA0 = *(const float4*)(xt + (m0 + la_m) * (SEQ * IDIM) + k0 + la_kt);
                pA1 = *(const float4*)(xt + (m0 + la_m + 32) * (SEQ * IDIM) + k0 + la_kt);
                pB  = *(const float4*)(Whx + (k0 + lb_k) * HID + n0 + lb_n);
            }
            As[grp][0][la_kt + 0][la_m] = pA0.x;
            As[grp][0][la_kt + 1][la_m] = pA0.y;
            As[grp][0][la_kt + 2][la_m] = pA0.z;
            As[grp][0][la_kt + 3][la_m] = pA0.w;
            As[grp][0][la_kt + 0][la_m + 32] = pA1.x;
            As[grp][0][la_kt + 1][la_m + 32] = pA1.y;
            As[grp][0][la_kt + 2][la_m + 32] = pA1.z;
            As[grp][0][la_kt + 3][la_m + 32] = pA1.w;
            Bs[grp][0][lb_k][lb_n + 0] = splat2(pB.x);
            Bs[grp][0][lb_k][lb_n + 1] = splat2(pB.y);
            Bs[grp][0][lb_k][lb_n + 2] = splat2(pB.z);
            Bs[grp][0][lb_k][lb_n + 3] = splat2(pB.w);
        }
        group_bar(grp);

        for (int ci = 0; ci < HALFC; ci++) {
            const int cb = ci & 1;
            const int cn = ci + 1;

            if (cn < HALFC) {
                const int c = cbase + cn;
                if (c < NCHUNK_H) {
                    const int k0 = c * KC;
                    pA0 = *(const float4*)(hcur + (m0 + la_m) * HID + k0 + la_kt);
                    pA1 = *(const float4*)(hcur + (m0 + la_m + 32) * HID + k0 + la_kt);
                    pB  = *(const float4*)(Whh + (k0 + lb_k) * HID + n0 + lb_n);
                } else {
                    const int k0 = (c - NCHUNK_H) * KC;
                    pA0 = *(const float4*)(xt + (m0 + la_m) * (SEQ * IDIM) + k0 + la_kt);
                    pA1 = *(const float4*)(xt + (m0 + la_m + 32) * (SEQ * IDIM) + k0 + la_kt);
                    pB  = *(const float4*)(Whx + (k0 + lb_k) * HID + n0 + lb_n);
                }
            }

            // compute 16 k-steps: 3 LDS + 8 FFMA2 per kk
            #pragma unroll
            for (int kk = 0; kk < KC; kk++) {
                ulonglong2 av = *(const ulonglong2*)&As[grp][cb][kk][4 * ty];
                ulonglong2 b01 = *(const ulonglong2*)&Bs[grp][cb][kk][4 * tx];
                ulonglong2 b23 = *(const ulonglong2*)&Bs[grp][cb][kk][4 * tx + 2];
                fma2(acc[0][0], av.x, b01.x);
                fma2(acc[0][1], av.x, b01.y);
                fma2(acc[0][2], av.x, b23.x);
                fma2(acc[0][3], av.x, b23.y);
                fma2(acc[1][0], av.y, b01.x);
                fma2(acc[1][1], av.y, b01.y);
                fma2(acc[1][2], av.y, b23.x);
                fma2(acc[1][3], av.y, b23.y);
            }

            if (cn < HALFC) {
                const int nb = cn & 1;
                As[grp][nb][la_kt + 0][la_m] = pA0.x;
                As[grp][nb][la_kt + 1][la_m] = pA0.y;
                As[grp][nb][la_kt + 2][la_m] = pA0.z;
                As[grp][nb][la_kt + 3][la_m] = pA0.w;
                As[grp][nb][la_kt + 0][la_m + 32] = pA1.x;
                As[grp][nb][la_kt + 1][la_m + 32] = pA1.y;
                As[grp][nb][la_kt + 2][la_m + 32] = pA1.z;
                As[grp][nb][la_kt + 3][la_m + 32] = pA1.w;
                Bs[grp][nb][lb_k][lb_n + 0] = splat2(pB.x);
                Bs[grp][nb][lb_k][lb_n + 1] = splat2(pB.y);
                Bs[grp][nb][lb_k][lb_n + 2] = splat2(pB.z);
                Bs[grp][nb][lb_k][lb_n + 3] = splat2(pB.w);
            }
            group_bar(grp);
        }

        // ---- combine K-halves, bias + tanh + store ----
        __syncthreads();
        if (grp == 0) {
            #pragma unroll
            for (int p = 0; p < 2; p++)
                #pragma unroll
                for (int j = 0; j < 4; j++) {
                    float2 c = unpk(acc[p][j]);
                    pacc[(p * 4 + j) * 2 + 0][ltid] = c.x;
                    pacc[(p * 4 + j) * 2 + 1][ltid] = c.y;
                }
        }
        __syncthreads();
        if (grp == 1) {
            float4 bhv = *(const float4*)(bh + n0 + 4 * tx);
            #pragma unroll
            for (int p = 0; p < 2; p++) {
                float2 c0 = unpk(acc[p][0]);
                float2 c1 = unpk(acc[p][1]);
                float2 c2 = unpk(acc[p][2]);
                float2 c3 = unpk(acc[p][3]);
                c0.x += pacc[(p * 4 + 0) * 2 + 0][ltid];
                c0.y += pacc[(p * 4 + 0) * 2 + 1][ltid];
                c1.x += pacc[(p * 4 + 1) * 2 + 0][ltid];
                c1.y += pacc[(p * 4 + 1) * 2 + 1][ltid];
                c2.x += pacc[(p * 4 + 2) * 2 + 0][ltid];
                c2.y += pacc[(p * 4 + 2) * 2 + 1][ltid];
                c3.x += pacc[(p * 4 + 3) * 2 + 0][ltid];
                c3.y += pacc[(p * 4 + 3) * 2 + 1][ltid];
                const int r = m0 + 4 * ty + 2 * p;
                float4 lo = make_float4(my_tanh(c0.x + bhv.x), my_tanh(c1.x + bhv.y),
                                        my_tanh(c2.x + bhv.z), my_tanh(c3.x + bhv.w));
                float4 hi = make_float4(my_tanh(c0.y + bhv.x), my_tanh(c1.y + bhv.y),
                                        my_tanh(c2.y + bhv.z), my_tanh(c3.y + bhv.w));
                *(float4*)(hnxt + r * HID + n0 + 4 * tx) = lo;
                *(float4*)(hnxt + (r + 1) * HID + n0 + 4 * tx) = hi;
            }
        }
        grid_sync();
    }

    // ---- classifier + softmax: 2 rows per CTA ----
    const float* hf = &g_h[0][0][0];   // SEQ even -> final h in buf 0
    const int lane = tid & 31;
    const int wrp  = tid >> 5;
    for (int rr = 0; rr < 2; rr++) {
        const int row = bid * 2 + rr;
        float a[OUTC];
        #pragma unroll
        for (int o = 0; o < OUTC; o++) a[o] = 0.f;
        for (int k = tid; k < HID; k += NTH) {
            float hv = hf[row * HID + k];
            const float* wr = Why + k * OUTC;
            #pragma unroll
            for (int o = 0; o < OUTC; o++) a[o] += hv * wr[o];
        }
        #pragma unroll
        for (int o = 0; o < OUTC; o++)
            #pragma unroll
            for (int off = 16; off > 0; off >>= 1)
                a[o] += __shfl_down_sync(0xffffffffu, a[o], off);
        if (lane == 0) {
            #pragma unroll
            for (int o = 0; o < OUTC; o++) red[wrp][o] = a[o];
        }
        __syncthreads();
        if (tid == 0) {
            float v[OUTC];
            float mx = -1e30f;
            #pragma unroll
            for (int o = 0; o < OUTC; o++) {
                float s8 = 0.f;
                #pragma unroll
                for (int w = 0; w < 8; w++) s8 += red[w][o];
                v[o] = s8 + bo[o];
                mx = fmaxf(mx, v[o]);
            }
            float s = 0.f;
            #pragma unroll
            for (int o = 0; o < OUTC; o++) { v[o] = expf(v[o] - mx); s += v[o]; }
            const float inv = 1.0f / s;
            #pragma unroll
            for (int o = 0; o < OUTC; o++) out[row * OUTC + o] = v[o] * inv;
        }
        __syncthreads();
    }
}

extern "C" void kernel_launch(void* const* d_in, const int* in_sizes, int n_in,
                              void* d_out, int out_size) {
    const float* x   = (const float*)d_in[0];
    const float* Whx = (const float*)d_in[1];
    const float* Whh = (const float*)d_in[2];
    const float* bh  = (const float*)d_in[3];
    const float* Why = (const float*)d_in[4];
    const float* bo  = (const float*)d_in[5];
    float* out = (float*)d_out;
    rnn_kernel<<<NCTA, NTH>>>(x, Whx, Whh, bh, Why, bo, out);
}

// round 4
// speedup vs baseline: 2.2792x; 2.2792x over previous
#include <cuda_runtime.h>
#include <math.h>

#define BATCH 256
#define SEQ   256
#define IDIM  128
#define HID   1024
#define OUTC  10

#define NCTA  128
#define NTH   256
#define MT    64
#define NT    32
#define KC    16
#define NCHUNK_H (HID / KC)            // 64
#define NCHUNK_X (IDIM / KC)           // 8
#define NCHUNK   (NCHUNK_H + NCHUNK_X) // 72
#define XC_PER_G (NCHUNK_X / 2)        // 4 x-chunks per group
#define HC_PER_G (NCHUNK_H / 2)        // 32 h-chunks per group

// Persistent state (device globals: no allocation allowed)
__device__ float g_h[2][BATCH][HID];
__device__ unsigned int g_bar;

// ---- packed f32x2 helpers ----
__device__ __forceinline__ unsigned long long splat2(float x) {
    unsigned long long r;
    asm("mov.b64 %0, {%1, %1};" : "=l"(r) : "f"(x));
    return r;
}
__device__ __forceinline__ void fma2(unsigned long long& acc,
                                     unsigned long long a,
                                     unsigned long long b) {
    asm("fma.rn.f32x2 %0, %1, %2, %0;" : "+l"(acc) : "l"(a), "l"(b));
}
__device__ __forceinline__ float2 unpk(unsigned long long v) {
    float2 r;
    asm("mov.b64 {%0, %1}, %2;" : "=f"(r.x), "=f"(r.y) : "l"(v));
    return r;
}

// Accurate tanh independent of fast-math tanh.approx (abs err ~5e-7).
__device__ __forceinline__ float my_tanh(float v) {
    float e = __expf(2.0f * v);
    return 1.0f - 2.0f / (e + 1.0f);
}

// group barrier: ids 1,2; 128 threads each
__device__ __forceinline__ void group_bar(int g) {
    asm volatile("bar.sync %0, 128;" :: "r"(g + 1) : "memory");
}

// Device-wide barrier: monotonic ticket counter (survives graph replays).
__device__ __forceinline__ void grid_sync() {
    __syncthreads();
    if (threadIdx.x == 0) {
        __threadfence();
        unsigned ticket = atomicAdd(&g_bar, 1u);
        unsigned target = (ticket / NCTA + 1u) * NCTA;
        volatile unsigned* p = &g_bar;
        while (*p < target) { }
    }
    __syncthreads();
    __threadfence();
}

__global__ void __launch_bounds__(NTH, 1)
rnn_kernel(const float* __restrict__ x,      // [B,S,I]
           const float* __restrict__ Whx,    // [I,H]
           const float* __restrict__ Whh,    // [H,H]
           const float* __restrict__ bh,     // [H]
           const float* __restrict__ Why,    // [H,OUT]
           const float* __restrict__ bo,     // [OUT]
           float* __restrict__ out)          // [B,OUT]
{
    __shared__ __align__(16) float As[2][2][KC][MT + 4];   // [grp][buf] k-major A
    __shared__ __align__(16) float Bs[2][2][KC][NT];       // [grp][buf] plain floats
    __shared__ float pacc[16][NTH / 2];
    __shared__ float red[8][OUTC];

    const int tid  = threadIdx.x;
    const int bid  = blockIdx.x;
    const int grp  = tid >> 7;          // 0/1: K-half
    const int ltid = tid & 127;

    const int mt = bid & 3;
    const int nt = bid >> 2;
    const int m0 = mt * MT;
    const int n0 = nt * NT;

    // loader lanes (within group)
    const int la_m  = ltid >> 2;        // 0..31 (+32 for 2nd half)
    const int la_kt = (ltid & 3) * 4;   // 0,4,8,12
    const int lb_k  = ltid >> 3;        // 0..15
    const int lb_n  = (ltid & 7) * 4;   // 0..28

    // compute lanes: 4x4 micro-tile
    const int tx = ltid & 7;            // 32 cols / 4
    const int ty = ltid >> 3;           // 64 rows / 4

    // ---- zero h buffer 0 ----
    {
        float4* p = (float4*)&g_h[0][0][0];
        const int total = BATCH * HID / 4;
        for (int i = bid * NTH + tid; i < total; i += NCTA * NTH)
            p[i] = make_float4(0.f, 0.f, 0.f, 0.f);
    }
    grid_sync();

    const float4 bhv = *(const float4*)(bh + n0 + 4 * tx);  // grp1 epilogue bias

    unsigned long long acc[2][4];
    float4 pA0, pA1, pB;

    for (int t = 0; t < SEQ; t++) {
        const float* __restrict__ hcur = &g_h[t & 1][0][0];
        float* __restrict__ hnxt = &g_h[(t + 1) & 1][0][0];
        const float* __restrict__ xt = x + t * IDIM;       // row stride SEQ*IDIM

        #pragma unroll
        for (int p = 0; p < 2; p++)
            #pragma unroll
            for (int j = 0; j < 4; j++)
                acc[p][j] = 0ull;

        // prefetch chunk c into regs
        auto pf = [&](int c) {
            if (c < NCHUNK_H) {
                const int k0 = c * KC;
                pA0 = *(const float4*)(hcur + (m0 + la_m) * HID + k0 + la_kt);
                pA1 = *(const float4*)(hcur + (m0 + la_m + 32) * HID + k0 + la_kt);
                pB  = *(const float4*)(Whh + (k0 + lb_k) * HID + n0 + lb_n);
            } else {
                const int k0 = (c - NCHUNK_H) * KC;
                pA0 = *(const float4*)(xt + (m0 + la_m) * (SEQ * IDIM) + k0 + la_kt);
                pA1 = *(const float4*)(xt + (m0 + la_m + 32) * (SEQ * IDIM) + k0 + la_kt);
                pB  = *(const float4*)(Whx + (k0 + lb_k) * HID + n0 + lb_n);
            }
        };
        // stage regs into smem buffer b
        auto stage = [&](int b) {
            As[grp][b][la_kt + 0][la_m] = pA0.x;
            As[grp][b][la_kt + 1][la_m] = pA0.y;
            As[grp][b][la_kt + 2][la_m] = pA0.z;
            As[grp][b][la_kt + 3][la_m] = pA0.w;
            As[grp][b][la_kt + 0][la_m + 32] = pA1.x;
            As[grp][b][la_kt + 1][la_m + 32] = pA1.y;
            As[grp][b][la_kt + 2][la_m + 32] = pA1.z;
            As[grp][b][la_kt + 3][la_m + 32] = pA1.w;
            *(float4*)&Bs[grp][b][lb_k][lb_n] = pB;
        };
        // consume 16 k-steps from buffer b: 2 LDS.128 + 4 splats + 8 FFMA2 per kk
        auto compute = [&](int b) {
            #pragma unroll
            for (int kk = 0; kk < KC; kk++) {
                ulonglong2 av = *(const ulonglong2*)&As[grp][b][kk][4 * ty];
                float4 bv = *(const float4*)&Bs[grp][b][kk][4 * tx];
                unsigned long long b0 = splat2(bv.x);
                unsigned long long b1 = splat2(bv.y);
                unsigned long long b2 = splat2(bv.z);
                unsigned long long b3 = splat2(bv.w);
                fma2(acc[0][0], av.x, b0);
                fma2(acc[0][1], av.x, b1);
                fma2(acc[0][2], av.x, b2);
                fma2(acc[0][3], av.x, b3);
                fma2(acc[1][0], av.y, b0);
                fma2(acc[1][1], av.y, b1);
                fma2(acc[1][2], av.y, b2);
                fma2(acc[1][3], av.y, b3);
            }
        };

        // ---- segment A: x-chunks (h-independent) BEFORE the grid barrier ----
        const int xbase = NCHUNK_H + grp * XC_PER_G;
        pf(xbase);
        stage(0);
        group_bar(grp);
        #pragma unroll
        for (int i = 0; i < XC_PER_G; i++) {
            if (i + 1 < XC_PER_G) pf(xbase + i + 1);
            compute(i & 1);
            if (i + 1 < XC_PER_G) stage((i + 1) & 1);
            group_bar(grp);
        }

        // barrier: h_t stores (from previous iteration's epilogue) now visible
        grid_sync();

        // ---- segment B: h-chunks ----
        const int hbase = grp * HC_PER_G;
        pf(hbase);
        stage(0);
        group_bar(grp);
        for (int i = 0; i < HC_PER_G; i++) {
            if (i + 1 < HC_PER_G) pf(hbase + i + 1);
            compute(i & 1);
            if (i + 1 < HC_PER_G) stage((i + 1) & 1);
            group_bar(grp);
        }

        // ---- combine K-halves, bias + tanh + store h_{t+1} ----
        __syncthreads();
        if (grp == 0) {
            #pragma unroll
            for (int p = 0; p < 2; p++)
                #pragma unroll
                for (int j = 0; j < 4; j++) {
                    float2 c = unpk(acc[p][j]);
                    pacc[(p * 4 + j) * 2 + 0][ltid] = c.x;
                    pacc[(p * 4 + j) * 2 + 1][ltid] = c.y;
                }
        }
        __syncthreads();
        if (grp == 1) {
            #pragma unroll
            for (int p = 0; p < 2; p++) {
                float2 c0 = unpk(acc[p][0]);
                float2 c1 = unpk(acc[p][1]);
                float2 c2 = unpk(acc[p][2]);
                float2 c3 = unpk(acc[p][3]);
                c0.x += pacc[(p * 4 + 0) * 2 + 0][ltid];
                c0.y += pacc[(p * 4 + 0) * 2 + 1][ltid];
                c1.x += pacc[(p * 4 + 1) * 2 + 0][ltid];
                c1.y += pacc[(p * 4 + 1) * 2 + 1][ltid];
                c2.x += pacc[(p * 4 + 2) * 2 + 0][ltid];
                c2.y += pacc[(p * 4 + 2) * 2 + 1][ltid];
                c3.x += pacc[(p * 4 + 3) * 2 + 0][ltid];
                c3.y += pacc[(p * 4 + 3) * 2 + 1][ltid];
                const int r = m0 + 4 * ty + 2 * p;
                float4 lo = make_float4(my_tanh(c0.x + bhv.x), my_tanh(c1.x + bhv.y),
                                        my_tanh(c2.x + bhv.z), my_tanh(c3.x + bhv.w));
                float4 hi = make_float4(my_tanh(c0.y + bhv.x), my_tanh(c1.y + bhv.y),
                                        my_tanh(c2.y + bhv.z), my_tanh(c3.y + bhv.w));
                *(float4*)(hnxt + r * HID + n0 + 4 * tx) = lo;
                *(float4*)(hnxt + (r + 1) * HID + n0 + 4 * tx) = hi;
            }
        }
        // NOTE: no trailing grid_sync — next iteration's x-segment overlaps
        // other CTAs' epilogues; the sync before its h-segment provides the
        // needed visibility (and the WAR separation for buffer reuse).
    }

    grid_sync();   // final h visible everywhere

    // ---- classifier + softmax: 2 rows per CTA ----
    const float* hf = &g_h[0][0][0];   // SEQ even -> final h in buf 0
    const int lane = tid & 31;
    const int wrp  = tid >> 5;
    for (int rr = 0; rr < 2; rr++) {
        const int row = bid * 2 + rr;
        float a[OUTC];
        #pragma unroll
        for (int o = 0; o < OUTC; o++) a[o] = 0.f;
        for (int k = tid; k < HID; k += NTH) {
            float hv = hf[row * HID + k];
            const float* wr = Why + k * OUTC;
            #pragma unroll
            for (int o = 0; o < OUTC; o++) a[o] += hv * wr[o];
        }
        #pragma unroll
        for (int o = 0; o < OUTC; o++)
            #pragma unroll
            for (int off = 16; off > 0; off >>= 1)
                a[o] += __shfl_down_sync(0xffffffffu, a[o], off);
        if (lane == 0) {
            #pragma unroll
            for (int o = 0; o < OUTC; o++) red[wrp][o] = a[o];
        }
        __syncthreads();
        if (tid == 0) {
            float v[OUTC];
            float mx = -1e30f;
            #pragma unroll
            for (int o = 0; o < OUTC; o++) {
                float s8 = 0.f;
                #pragma unroll
                for (int w = 0; w < 8; w++) s8 += red[w][o];
                v[o] = s8 + bo[o];
                mx = fmaxf(mx, v[o]);
            }
            float s = 0.f;
            #pragma unroll
            for (int o = 0; o < OUTC; o++) { v[o] = expf(v[o] - mx); s += v[o]; }
            const float inv = 1.0f / s;
            #pragma unroll
            for (int o = 0; o < OUTC; o++) out[row * OUTC + o] = v[o] * inv;
        }
        __syncthreads();
    }
}

extern "C" void kernel_launch(void* const* d_in, const int* in_sizes, int n_in,
                              void* d_out, int out_size) {
    const float* x   = (const float*)d_in[0];
    const float* Whx = (const float*)d_in[1];
    const float* Whh = (const float*)d_in[2];
    const float* bh  = (const float*)d_in[3];
    const float* Why = (const float*)d_in[4];
    const float* bo  = (const float*)d_in[5];
    float* out = (float*)d_out;
    rnn_kernel<<<NCTA, NTH>>>(x, Whx, Whh, bh, Why, bo, out);
}

// round 5
// speedup vs baseline: 3.0261x; 1.3277x over previous
#include <cuda_runtime.h>
#include <stdint.h>
#include <math.h>

#define BATCH 256
#define SEQ   256
#define IDIM  128
#define HID   1024
#define KEFF  1152
#define OUTC  10

#define NCTA   128
#define NTH    256
#define NSPLIT 8
#define KPC    144          // K per CTA (KEFF / NSPLIT)
#define NCHK   9            // chunks of 16 k
#define SROW   20           // smem row stride (floats), conflict-free for frags

// -------- device globals (no allocation allowed) --------
__device__ float  g_h[BATCH * HID];            // hidden state (fp32)
__device__ float  g_wt[HID * KEFF];            // Wt[n][k] = [Whh;Whx][k][n]
__device__ float4 g_part[NCTA * 8 * 16 * 32];  // [bid][warp][q][lane] partials, 8MB
__device__ unsigned int g_bar;                 // monotonic grid barrier

// -------- helpers --------
static __device__ __forceinline__ void split_tf32(float v, uint32_t& hi, uint32_t& lo) {
    uint32_t h;
    asm("cvt.rna.tf32.f32 %0, %1;" : "=r"(h) : "f"(v));
    hi = h;
    float l = v - __uint_as_float(h);
    asm("cvt.rna.tf32.f32 %0, %1;" : "=r"(lo) : "f"(l));
}
static __device__ __forceinline__ void mma8(float* c, const uint32_t* a,
                                            uint32_t b0, uint32_t b1) {
    asm volatile(
        "mma.sync.aligned.m16n8k8.row.col.f32.tf32.tf32.f32 "
        "{%0,%1,%2,%3},{%4,%5,%6,%7},{%8,%9},{%0,%1,%2,%3};"
        : "+f"(c[0]), "+f"(c[1]), "+f"(c[2]), "+f"(c[3])
        : "r"(a[0]), "r"(a[1]), "r"(a[2]), "r"(a[3]), "r"(b0), "r"(b1));
}
static __device__ __forceinline__ float my_tanh(float v) {
    float e = __expf(2.0f * v);
    return 1.0f - 2.0f / (e + 1.0f);
}
static __device__ __forceinline__ void grid_sync() {
    __syncthreads();
    if (threadIdx.x == 0) {
        __threadfence();
        unsigned ticket = atomicAdd(&g_bar, 1u);
        unsigned target = (ticket / NCTA + 1u) * NCTA;
        volatile unsigned* p = &g_bar;
        while (*p < target) { }
    }
    __syncthreads();
    __threadfence();
}

// -------- prep: transpose weights, zero h --------
__global__ void prep_kernel(const float* __restrict__ Whx,
                            const float* __restrict__ Whh) {
    const int tid = blockIdx.x * blockDim.x + threadIdx.x;
    const int nt  = gridDim.x * blockDim.x;
    for (int i = tid; i < HID * KEFF; i += nt) {
        int n = i / KEFF, k = i - n * KEFF;
        g_wt[i] = (k < HID) ? Whh[k * HID + n] : Whx[(k - HID) * HID + n];
    }
    for (int i = tid; i < BATCH * HID; i += nt) g_h[i] = 0.f;
}

// -------- main persistent kernel --------
__global__ void __launch_bounds__(NTH, 1)
rnn_kernel(const float* __restrict__ x,      // [B,S,I]
           const float* __restrict__ bh,     // [H]
           const float* __restrict__ Why,    // [H,OUT]
           const float* __restrict__ bo,     // [OUT]
           float* __restrict__ out)          // [B,OUT]
{
    __shared__ __align__(16) float sA[2][128 * SROW];   // 10KB x2
    __shared__ __align__(16) float sB[2][128 * SROW];   // 10KB x2
    __shared__ float red[8][OUTC];

    const int tid  = threadIdx.x;
    const int bid  = blockIdx.x;
    const int wid  = tid >> 5;
    const int lane = tid & 31;

    const int tile  = bid >> 3;       // 0..15
    const int ks    = bid & 7;        // K-split index
    const int tileM = tile >> 3;      // 0..1
    const int tileN = tile & 7;       // 0..7
    const int m0    = tileM * 128;
    const int n0    = tileN * 128;
    const int kbase = ks * KPC;

    const int wm  = wid >> 2;         // warp row (0..1) -> 64 rows
    const int wn  = wid & 3;          // warp col (0..3) -> 32 cols
    const int grp = lane >> 2;        // 0..7
    const int tig = lane & 3;         // 0..3

    // loader lanes: 128 rows x 16 k, 2 float4 per thread (A and B identical shape)
    const int lrow = tid >> 1;        // 0..127
    const int lq   = (tid & 1) * 8;   // float offset 0 or 8

    float acc[4][4][4];

    for (int t = 0; t < SEQ; t++) {
        // ================= MMA phase =================
        #pragma unroll
        for (int mt = 0; mt < 4; mt++)
            #pragma unroll
            for (int nt = 0; nt < 4; nt++)
                #pragma unroll
                for (int c = 0; c < 4; c++)
                    acc[mt][nt][c] = 0.f;

        float4 av0, av1, bv0, bv1;

        // prefetch chunk 0
        {
            const int kg = kbase;
            const float* asrc = (kg < HID)
                ? (g_h + (m0 + lrow) * HID + kg)
                : (x + (long)(m0 + lrow) * (SEQ * IDIM) + (long)t * IDIM + (kg - HID));
            av0 = *(const float4*)(asrc + lq);
            av1 = *(const float4*)(asrc + lq + 4);
            const float* bsrc = g_wt + (long)(n0 + lrow) * KEFF + kg;
            bv0 = *(const float4*)(bsrc + lq);
            bv1 = *(const float4*)(bsrc + lq + 4);
        }
        *(float4*)(sA[0] + lrow * SROW + lq)     = av0;
        *(float4*)(sA[0] + lrow * SROW + lq + 4) = av1;
        *(float4*)(sB[0] + lrow * SROW + lq)     = bv0;
        *(float4*)(sB[0] + lrow * SROW + lq + 4) = bv1;
        __syncthreads();

        for (int c = 0; c < NCHK; c++) {
            const int buf = c & 1;

            // prefetch next chunk
            if (c + 1 < NCHK) {
                const int kg = kbase + (c + 1) * 16;
                const float* asrc = (kg < HID)
                    ? (g_h + (m0 + lrow) * HID + kg)
                    : (x + (long)(m0 + lrow) * (SEQ * IDIM) + (long)t * IDIM + (kg - HID));
                av0 = *(const float4*)(asrc + lq);
                av1 = *(const float4*)(asrc + lq + 4);
                const float* bsrc = g_wt + (long)(n0 + lrow) * KEFF + kg;
                bv0 = *(const float4*)(bsrc + lq);
                bv1 = *(const float4*)(bsrc + lq + 4);
            }

            // compute 2 k8 slices from this buffer
            #pragma unroll
            for (int k8 = 0; k8 < 2; k8++) {
                uint32_t aH[4][4], aL[4][4];
                #pragma unroll
                for (int mt = 0; mt < 4; mt++) {
                    const float* p = sA[buf] + (wm * 64 + mt * 16 + grp) * SROW
                                   + k8 * 8 + tig;
                    split_tf32(p[0],         aH[mt][0], aL[mt][0]);
                    split_tf32(p[8 * SROW],  aH[mt][1], aL[mt][1]);
                    split_tf32(p[4],         aH[mt][2], aL[mt][2]);
                    split_tf32(p[8 * SROW + 4], aH[mt][3], aL[mt][3]);
                }
                #pragma unroll
                for (int nt = 0; nt < 4; nt++) {
                    const float* q = sB[buf] + (wn * 32 + nt * 8 + grp) * SROW
                                   + k8 * 8 + tig;
                    uint32_t bH0, bL0, bH1, bL1;
                    split_tf32(q[0], bH0, bL0);
                    split_tf32(q[4], bH1, bL1);
                    #pragma unroll
                    for (int mt = 0; mt < 4; mt++) {
                        mma8(acc[mt][nt], aH[mt], bH0, bH1);
                        mma8(acc[mt][nt], aH[mt], bL0, bL1);
                        mma8(acc[mt][nt], aL[mt], bH0, bH1);
                    }
                }
            }

            // stage next chunk
            if (c + 1 < NCHK) {
                const int nb = buf ^ 1;
                *(float4*)(sA[nb] + lrow * SROW + lq)     = av0;
                *(float4*)(sA[nb] + lrow * SROW + lq + 4) = av1;
                *(float4*)(sB[nb] + lrow * SROW + lq)     = bv0;
                *(float4*)(sB[nb] + lrow * SROW + lq + 4) = bv1;
            }
            __syncthreads();
        }

        // store partials (raw fragment layout, fully coalesced)
        {
            float4* pp = g_part + ((long)(bid * 8 + wid) * 16) * 32 + lane;
            #pragma unroll
            for (int mt = 0; mt < 4; mt++)
                #pragma unroll
                for (int nt = 0; nt < 4; nt++) {
                    const int q = mt * 4 + nt;
                    pp[q * 32] = make_float4(acc[mt][nt][0], acc[mt][nt][1],
                                             acc[mt][nt][2], acc[mt][nt][3]);
                }
        }
        grid_sync();

        // ================= reduce phase =================
        {
            const int slot = tid >> 5;
            #pragma unroll
            for (int it = 0; it < 2; it++) {
                const int p  = ks * 16 + slot + it * 8;   // (w,q) pair index
                const int w  = p >> 4;
                const int qq = p & 15;
                float s0 = 0.f, s1 = 0.f, s2 = 0.f, s3 = 0.f;
                #pragma unroll
                for (int k2 = 0; k2 < 8; k2++) {
                    float4 v = g_part[ ((long)((tile * 8 + k2) * 8 + w) * 16 + qq) * 32 + lane ];
                    s0 += v.x; s1 += v.y; s2 += v.z; s3 += v.w;
                }
                const int wm_ = w >> 2, wn_ = w & 3;
                const int mt = qq >> 2, nt = qq & 3;
                const int gg = lane >> 2, tg = lane & 3;
                const int m = m0 + wm_ * 64 + mt * 16 + gg;
                const int n = n0 + wn_ * 32 + nt * 8 + tg * 2;
                const float b0v = bh[n], b1v = bh[n + 1];
                float2 r0 = make_float2(my_tanh(s0 + b0v), my_tanh(s1 + b1v));
                float2 r1 = make_float2(my_tanh(s2 + b0v), my_tanh(s3 + b1v));
                *(float2*)(g_h + m * HID + n)        = r0;
                *(float2*)(g_h + (m + 8) * HID + n)  = r1;
            }
        }
        grid_sync();
    }

    // ================= classifier + softmax: 2 rows per CTA =================
    for (int rr = 0; rr < 2; rr++) {
        const int row = bid * 2 + rr;
        float a[OUTC];
        #pragma unroll
        for (int o = 0; o < OUTC; o++) a[o] = 0.f;
        for (int k = tid; k < HID; k += NTH) {
            float hv = g_h[row * HID + k];
            const float* wr = Why + k * OUTC;
            #pragma unroll
            for (int o = 0; o < OUTC; o++) a[o] += hv * wr[o];
        }
        #pragma unroll
        for (int o = 0; o < OUTC; o++)
            #pragma unroll
            for (int off = 16; off > 0; off >>= 1)
                a[o] += __shfl_down_sync(0xffffffffu, a[o], off);
        if (lane == 0) {
            #pragma unroll
            for (int o = 0; o < OUTC; o++) red[wid][o] = a[o];
        }
        __syncthreads();
        if (tid == 0) {
            float v[OUTC];
            float mx = -1e30f;
            #pragma unroll
            for (int o = 0; o < OUTC; o++) {
                float s8 = 0.f;
                #pragma unroll
                for (int w = 0; w < 8; w++) s8 += red[w][o];
                v[o] = s8 + bo[o];
                mx = fmaxf(mx, v[o]);
            }
            float s = 0.f;
            #pragma unroll
            for (int o = 0; o < OUTC; o++) { v[o] = expf(v[o] - mx); s += v[o]; }
            const float inv = 1.0f / s;
            #pragma unroll
            for (int o = 0; o < OUTC; o++) out[row * OUTC + o] = v[o] * inv;
        }
        __syncthreads();
    }
}

extern "C" void kernel_launch(void* const* d_in, const int* in_sizes, int n_in,
                              void* d_out, int out_size) {
    const float* x   = (const float*)d_in[0];
    const float* Whx = (const float*)d_in[1];
    const float* Whh = (const float*)d_in[2];
    const float* bh  = (const float*)d_in[3];
    const float* Why = (const float*)d_in[4];
    const float* bo  = (const float*)d_in[5];
    float* out = (float*)d_out;
    prep_kernel<<<1024, 256>>>(Whx, Whh);
    rnn_kernel<<<NCTA, NTH>>>(x, bh, Why, bo, out);
}